// round 17
// baseline (speedup 1.0000x reference)
#include <cuda_runtime.h>
#include <math.h>

// Problem constants (fixed by the dataset)
#define NMAX 50000
#define EMAX 800000

// ---------------- scratch (device globals; no allocation allowed) ----------
__device__ float    g_q [NMAX * 64];
__device__ float    g_k [NMAX * 64];
__device__ float    g_v [NMAX * 64];
__device__ float    g_pa[NMAX * 64];      // P_a = nn @ W1[0:64]
__device__ float    g_pb[NMAX * 64];      // P_b = nn @ W1[64:128]
__device__ float    g_agg[NMAX * 64];     // attention aggregate (unnormalized)
__device__ float    g_denom[NMAX * 4];    // softmax denominators (no max-sub)
__device__ float    g_w1abt[2 * 4096];    // W1a^T, W1b^T (plain transposed tf32)
__device__ float    g_w1cf[4096];         // W1c in per-lane MMA fragment order
__device__ float    g_wef[4096];          // We  in per-lane MMA fragment order
__device__ int      g_idx64;              // 1 if edge_index is int64

// ---------------- index width handling --------------------------------------
__device__ __forceinline__ long long ld_idx(const void* p, long long i) {
    if (g_idx64) return ((const long long*)p)[i];
    return (long long)((const int*)p)[i];
}

// round fp32 -> tf32 (rna), keep in fp32 bit container
__device__ __forceinline__ float cvt_tf32(float x) {
    unsigned u;
    asm("cvt.rna.tf32.f32 %0, %1;" : "=r"(u) : "f"(x));
    return __uint_as_float(u);
}

__device__ __forceinline__ float gelu_exact(float x) {
    return 0.5f * x * (1.0f + erff(x * 0.70710678118654752f));
}

// ---------------- 8-warp 64x64x64 smem-B GEMM (qkv / projo) ------------------
__device__ __forceinline__ void mma_gemm64(const float (*A)[68], const float (*Bt)[68],
                                           float c[4][4], int lane, int m0, int n0) {
    int row = lane >> 2, col = lane & 3;
#pragma unroll
    for (int k0 = 0; k0 < 64; k0 += 8) {
        unsigned a0 = __float_as_uint(A[m0 + row][k0 + col]);
        unsigned a1 = __float_as_uint(A[m0 + row + 8][k0 + col]);
        unsigned a2 = __float_as_uint(A[m0 + row][k0 + col + 4]);
        unsigned a3 = __float_as_uint(A[m0 + row + 8][k0 + col + 4]);
#pragma unroll
        for (int nt = 0; nt < 4; nt++) {
            unsigned b0 = __float_as_uint(Bt[n0 + nt * 8 + row][k0 + col]);
            unsigned b1 = __float_as_uint(Bt[n0 + nt * 8 + row][k0 + col + 4]);
            asm volatile(
                "mma.sync.aligned.m16n8k8.row.col.f32.tf32.tf32.f32 "
                "{%0,%1,%2,%3}, {%4,%5,%6,%7}, {%8,%9}, {%0,%1,%2,%3};"
                : "+f"(c[nt][0]), "+f"(c[nt][1]), "+f"(c[nt][2]), "+f"(c[nt][3])
                : "r"(a0), "r"(a1), "r"(a2), "r"(a3), "r"(b0), "r"(b1));
        }
    }
}

// ---------------- 4-warp 32x32-per-warp GEMM, B from global fragments --------
__device__ __forceinline__ void mma_warp32(const float (*A)[76],
                                           const float* __restrict__ bfrag,
                                           float c[2][4][4], int lane, int m0) {
    int row = lane >> 2, col = lane & 3;
#pragma unroll
    for (int kk = 0; kk < 8; kk++) {
        unsigned a[2][4];
#pragma unroll
        for (int ms = 0; ms < 2; ms++) {
            int r = m0 + ms * 16 + row;
            a[ms][0] = __float_as_uint(A[r][kk * 8 + col]);
            a[ms][1] = __float_as_uint(A[r + 8][kk * 8 + col]);
            a[ms][2] = __float_as_uint(A[r][kk * 8 + col + 4]);
            a[ms][3] = __float_as_uint(A[r + 8][kk * 8 + col + 4]);
        }
#pragma unroll
        for (int nt = 0; nt < 4; nt++) {
            float2 bf = *(const float2*)&bfrag[kk * 512 + nt * 64 + lane * 2];
            unsigned b0 = __float_as_uint(bf.x), b1 = __float_as_uint(bf.y);
#pragma unroll
            for (int ms = 0; ms < 2; ms++) {
                asm volatile(
                    "mma.sync.aligned.m16n8k8.row.col.f32.tf32.tf32.f32 "
                    "{%0,%1,%2,%3}, {%4,%5,%6,%7}, {%8,%9}, {%0,%1,%2,%3};"
                    : "+f"(c[ms][nt][0]), "+f"(c[ms][nt][1]),
                      "+f"(c[ms][nt][2]), "+f"(c[ms][nt][3])
                    : "r"(a[ms][0]), "r"(a[ms][1]), "r"(a[ms][2]), "r"(a[ms][3]),
                      "r"(b0), "r"(b1));
            }
        }
    }
}

// ---------------- K1: QKV (3x blocks) + detect + zero + weight prep ----------
__global__ void qkv_kernel(const float* __restrict__ nf,
                           const float* __restrict__ Wq,
                           const float* __restrict__ Wk,
                           const float* __restrict__ Wv,
                           const float* __restrict__ W1,
                           const float* __restrict__ We,
                           const void* __restrict__ eidx,
                           int Nn, long long E) {
    int t = threadIdx.x;
    int bid = blockIdx.x;

    // detect int64 vs int32 edge_index (block 0)
    if (bid == 0) {
        __shared__ int s_nz;
        if (t == 0) s_nz = 0;
        __syncthreads();
        int ns = (int)(E < 1024 ? E : 1024);
        const int* w = (const int*)eidx;
        int nz = 0;
        for (int i = t; i < ns; i += 256)
            if (w[2 * i + 1] != 0) nz = 1;
        if (nz) atomicOr(&s_nz, 1);
        __syncthreads();
        if (t == 0) g_idx64 = s_nz ? 0 : 1;
    }

    // one-time weight prep (blocks 1-4)
    if (bid == 1 || bid == 2) {     // W1a^T / W1b^T for projo
        int ch = bid - 1;
        for (int i = t; i < 4096; i += 256) {
            int k = i >> 6, j = i & 63;
            g_w1abt[ch * 4096 + j * 64 + k] =
                cvt_tf32(W1[(size_t)(ch * 64 + k) * 64 + j]);
        }
    }
    if (bid == 3) {                 // W1c fragments for edge_mlp
        for (int fi = t; fi < 2048; fi += 256) {
            int lane = fi & 31, nt = (fi >> 5) & 3, nh = (fi >> 7) & 1, kk = fi >> 8;
            int n = nh * 32 + nt * 8 + (lane >> 2);
            int k = 128 + kk * 8 + (lane & 3);
            g_w1cf[fi * 2]     = cvt_tf32(W1[(size_t)k * 64 + n]);
            g_w1cf[fi * 2 + 1] = cvt_tf32(W1[(size_t)(k + 4) * 64 + n]);
        }
    }
    if (bid == 4) {                 // We fragments for edge_fused
        for (int fi = t; fi < 2048; fi += 256) {
            int lane = fi & 31, nt = (fi >> 5) & 3, nh = (fi >> 7) & 1, kk = fi >> 8;
            int n = nh * 32 + nt * 8 + (lane >> 2);
            int k = kk * 8 + (lane & 3);
            g_wef[fi * 2]     = cvt_tf32(We[k * 64 + n]);
            g_wef[fi * 2 + 1] = cvt_tf32(We[(k + 4) * 64 + n]);
        }
    }

    // grid-stride zero of accumulators
    long long stride = (long long)gridDim.x * 256;
    for (long long i = (long long)bid * 256 + t; i < (long long)Nn * 64; i += stride)
        g_agg[i] = 0.0f;
    for (long long i = (long long)bid * 256 + t; i < (long long)Nn * 4; i += stride)
        g_denom[i] = 0.0f;

    // projection: one 64x64 output tile (matrix m = bid%3)
    int m = bid % 3;
    int tile = bid / 3;
    const float* W = (m == 0) ? Wq : (m == 1) ? Wk : Wv;
    float* Y = (m == 0) ? g_q : (m == 1) ? g_k : g_v;
    int r0 = tile * 64;

    __shared__ float Xs[64][68];
    __shared__ float Wt[64][68];
    for (int i = t; i < 4096; i += 256) {
        int k = i >> 6, j = i & 63;
        Wt[j][k] = cvt_tf32(W[k * 64 + j]);
    }
    for (int i = t; i < 1024; i += 256) {
        int row = i >> 4, d4 = (i & 15) * 4;
        int r = r0 + row;
        float4 v = (r < Nn) ? *(const float4*)&nf[(size_t)r * 64 + d4]
                            : make_float4(0.f, 0.f, 0.f, 0.f);
        Xs[row][d4]     = cvt_tf32(v.x);
        Xs[row][d4 + 1] = cvt_tf32(v.y);
        Xs[row][d4 + 2] = cvt_tf32(v.z);
        Xs[row][d4 + 3] = cvt_tf32(v.w);
    }
    __syncthreads();

    int wid = t >> 5, lane = t & 31;
    int m0 = (wid & 3) * 16, n0 = (wid >> 2) * 32;
    float c[4][4] = {};
    mma_gemm64(Xs, Wt, c, lane, m0, n0);

    int rlo = r0 + m0 + (lane >> 2);
#pragma unroll
    for (int nt = 0; nt < 4; nt++) {
        int cb = n0 + nt * 8 + (lane & 3) * 2;
        if (rlo < Nn)
            *(float2*)&Y[(size_t)rlo * 64 + cb] = make_float2(c[nt][0], c[nt][1]);
        if (rlo + 8 < Nn)
            *(float2*)&Y[(size_t)(rlo + 8) * 64 + cb] = make_float2(c[nt][2], c[nt][3]);
    }
}

// ---------------- K2: FUSED ep-GEMM + scores + exp + denom + aggregation -----
__global__ void __launch_bounds__(128, 8)
edge_fused_kernel(const float* __restrict__ EF,
                  const void* __restrict__ eidx,
                  long long E) {
    __shared__ float Xs[64][76];    // EF (tf32) -> then EP tile
    __shared__ long long srcs[64], tgts[64];
    int t = threadIdx.x;
    long long e0 = (long long)blockIdx.x * 64;

    if (t < 64) {
        long long eg = e0 + t;
        srcs[t] = (eg < E) ? ld_idx(eidx, eg)     : 0;
        tgts[t] = (eg < E) ? ld_idx(eidx, E + eg) : 0;
    }
    for (int i = t; i < 1024; i += 128) {
        int e = i >> 4, d4 = (i & 15) * 4;
        long long eg = e0 + e;
        float4 v = (eg < E) ? *(const float4*)&EF[eg * 64 + d4]
                            : make_float4(0.f, 0.f, 0.f, 0.f);
        v.x = cvt_tf32(v.x); v.y = cvt_tf32(v.y);
        v.z = cvt_tf32(v.z); v.w = cvt_tf32(v.w);
        *(float4*)&Xs[e][d4] = v;
    }
    __syncthreads();

    int wid = t >> 5, lane = t & 31;
    int m0 = (wid & 1) * 32, nh = wid >> 1;
    float c[2][4][4] = {};
    mma_warp32(Xs, g_wef + nh * 256, c, lane, m0);
    __syncthreads();   // all warps done reading Xs

    // scatter EP into Xs (float2 stores)
    int row = lane >> 2, col2 = (lane & 3) * 2;
#pragma unroll
    for (int ms = 0; ms < 2; ms++) {
        int r = m0 + ms * 16 + row;
#pragma unroll
        for (int nt = 0; nt < 4; nt++) {
            int cb = nh * 32 + nt * 8 + col2;
            *(float2*)&Xs[r][cb]     = make_float2(c[ms][nt][0], c[ms][nt][1]);
            *(float2*)&Xs[r + 8][cb] = make_float2(c[ms][nt][2], c[ms][nt][3]);
        }
    }
    __syncthreads();

    // coalesced attention epilogue: 4 rounds of 4 edges per warp
    {
        int s = lane & 7;            // sublane: dims {4s..4s+3, 32+4s..}
        int g = lane >> 3;           // edge group within warp
#pragma unroll
        for (int r = 0; r < 4; r++) {
            int e = wid * 16 + r * 4 + g;
            long long eg = e0 + e;
            long long sidx = srcs[e], tidx = tgts[e];
            float4 q0 = *(const float4*)&g_q[tidx * 64 + s * 4];
            float4 q1 = *(const float4*)&g_q[tidx * 64 + 32 + s * 4];
            float4 k0 = *(const float4*)&g_k[sidx * 64 + s * 4];
            float4 k1 = *(const float4*)&g_k[sidx * 64 + 32 + s * 4];
            float4 v0 = *(const float4*)&g_v[sidx * 64 + s * 4];
            float4 v1 = *(const float4*)&g_v[sidx * 64 + 32 + s * 4];
            float4 p0 = *(const float4*)&Xs[e][s * 4];
            float4 p1 = *(const float4*)&Xs[e][32 + s * 4];
            float dlo = q0.x * (k0.x + p0.x) + q0.y * (k0.y + p0.y)
                      + q0.z * (k0.z + p0.z) + q0.w * (k0.w + p0.w);
            float dhi = q1.x * (k1.x + p1.x) + q1.y * (k1.y + p1.y)
                      + q1.z * (k1.z + p1.z) + q1.w * (k1.w + p1.w);
            dlo += __shfl_xor_sync(0xffffffffu, dlo, 1);
            dhi += __shfl_xor_sync(0xffffffffu, dhi, 1);
            dlo += __shfl_xor_sync(0xffffffffu, dlo, 2);
            dhi += __shfl_xor_sync(0xffffffffu, dhi, 2);
            float exlo = __expf(dlo * 0.25f);   // head (s>>2)     : dims low
            float exhi = __expf(dhi * 0.25f);   // head (s>>2) + 2 : dims high
            if (eg < E) {
                if ((s & 3) == 0) {
                    atomicAdd(&g_denom[tidx * 4 + (s >> 2)], exlo);
                    atomicAdd(&g_denom[tidx * 4 + 2 + (s >> 2)], exhi);
                }
                float* dst = &g_agg[tidx * 64 + s * 4];
                float x = exlo * (v0.x + p0.x), y = exlo * (v0.y + p0.y);
                float z = exlo * (v0.z + p0.z), w = exlo * (v0.w + p0.w);
                asm volatile("red.global.add.v4.f32 [%0], {%1, %2, %3, %4};"
                             :: "l"(dst), "f"(x), "f"(y), "f"(z), "f"(w) : "memory");
                x = exhi * (v1.x + p1.x); y = exhi * (v1.y + p1.y);
                z = exhi * (v1.z + p1.z); w = exhi * (v1.w + p1.w);
                asm volatile("red.global.add.v4.f32 [%0], {%1, %2, %3, %4};"
                             :: "l"(dst + 32), "f"(x), "f"(y), "f"(z), "f"(w) : "memory");
            }
        }
    }
}

// ---------------- K3: proj_o + ONE MLP partial per block ---------------------
// bid = tile*2 + ab. Both blocks of a tile compute nn identically
// (deterministic MMA), then each writes its own P (ab=0 -> P_a, 1 -> P_b).
__global__ void projo_kernel(const float* __restrict__ nf,
                             const float* __restrict__ Wo, int Nn) {
    __shared__ float Xs[64][68];
    __shared__ float Wt[64][68];
    int t = threadIdx.x;
    int tile = blockIdx.x >> 1;
    int ab = blockIdx.x & 1;
    int r0 = tile * 64;
    int wid = t >> 5, lane = t & 31;
    int m0 = (wid & 3) * 16, n0 = (wid >> 2) * 32;

    for (int i = t; i < 4096; i += 256) {
        int k = i >> 6, j = i & 63;
        Wt[j][k] = cvt_tf32(Wo[k * 64 + j]);
    }
    for (int i = t; i < 4096; i += 256) {
        int row = i >> 6, d = i & 63;
        int r = r0 + row;
        float val = 0.0f;
        if (r < Nn) {
            float dn = g_denom[r * 4 + (d >> 4)];
            val = cvt_tf32(g_agg[(size_t)r * 64 + d] / (dn + 1e-9f));
        }
        Xs[row][d] = val;
    }
    __syncthreads();

    float c[4][4] = {};
    mma_gemm64(Xs, Wt, c, lane, m0, n0);
    __syncthreads();   // all warps done reading Xs

    // nn = c + residual (tf32-rounded), into Xs (smem only)
    {
        int rl = m0 + (lane >> 2);
#pragma unroll
        for (int nt = 0; nt < 4; nt++) {
            int cb = n0 + nt * 8 + (lane & 3) * 2;
            float2 b0 = make_float2(0.f, 0.f), b1 = make_float2(0.f, 0.f);
            if (r0 + rl < Nn)     b0 = *(const float2*)&nf[(size_t)(r0 + rl) * 64 + cb];
            if (r0 + rl + 8 < Nn) b1 = *(const float2*)&nf[(size_t)(r0 + rl + 8) * 64 + cb];
            Xs[rl][cb]     = cvt_tf32(c[nt][0] + b0.x);
            Xs[rl][cb + 1] = cvt_tf32(c[nt][1] + b0.y);
            Xs[rl + 8][cb]     = cvt_tf32(c[nt][2] + b1.x);
            Xs[rl + 8][cb + 1] = cvt_tf32(c[nt][3] + b1.y);
        }
    }
    __syncthreads();

    // this block's MLP partial GEMM
    for (int i = t; i < 1024; i += 256) {
        float4 w = *(const float4*)&g_w1abt[ab * 4096 + i * 4];
        int r = i >> 4, c4 = (i & 15) * 4;
        *(float4*)&Wt[r][c4] = w;
    }
    __syncthreads();
    float c2[4][4] = {};
    mma_gemm64(Xs, Wt, c2, lane, m0, n0);
    float* P = ab ? g_pb : g_pa;
    int rlo = r0 + m0 + (lane >> 2);
#pragma unroll
    for (int nt = 0; nt < 4; nt++) {
        int cb = n0 + nt * 8 + (lane & 3) * 2;
        if (rlo < Nn)
            *(float2*)&P[(size_t)rlo * 64 + cb] = make_float2(c2[nt][0], c2[nt][1]);
        if (rlo + 8 < Nn)
            *(float2*)&P[(size_t)(rlo + 8) * 64 + cb] = make_float2(c2[nt][2], c2[nt][3]);
    }
}

// ---------------- K4: edge classifier MLP (single MMA chunk) -----------------
__global__ void __launch_bounds__(128, 8)
edge_mlp_kernel(const float* __restrict__ EF,
                const float* __restrict__ b1,
                const float* __restrict__ W2,
                const float* __restrict__ b2,
                const void* __restrict__ eidx,
                float* __restrict__ out, long long E) {
    __shared__ float Xs[64][76];      // ef tile (tf32) -> then C tile
    __shared__ long long srcs[64], tgts[64];
    __shared__ float b1s[64];
    __shared__ float W2s[128];
    __shared__ float b2s[2];
    int t = threadIdx.x;
    long long e0 = (long long)blockIdx.x * 64;

    if (t < 64)  b1s[t] = b1[t];
    if (t >= 64 && t < 66) b2s[t - 64] = b2[t - 64];
    if (t < 128) W2s[t] = W2[t];
    if (t < 64) {
        long long eg = e0 + t;
        srcs[t] = (eg < E) ? ld_idx(eidx, eg)     : 0;
        tgts[t] = (eg < E) ? ld_idx(eidx, E + eg) : 0;
    }
    for (int i = t; i < 1024; i += 128) {
        int e = i >> 4, d4 = (i & 15) * 4;
        long long eg = e0 + e;
        float4 v = (eg < E) ? *(const float4*)&EF[eg * 64 + d4]
                            : make_float4(0.f, 0.f, 0.f, 0.f);
        v.x = cvt_tf32(v.x); v.y = cvt_tf32(v.y);
        v.z = cvt_tf32(v.z); v.w = cvt_tf32(v.w);
        *(float4*)&Xs[e][d4] = v;
    }
    __syncthreads();

    int wid = t >> 5, lane = t & 31;
    int m0 = (wid & 1) * 32, nh = wid >> 1;
    float c[2][4][4] = {};
    mma_warp32(Xs, g_w1cf + nh * 256, c, lane, m0);
    __syncthreads();   // all warps done reading Xs

    // scatter C into Xs (float2 stores)
    int row = lane >> 2, col2 = (lane & 3) * 2;
#pragma unroll
    for (int ms = 0; ms < 2; ms++) {
        int r = m0 + ms * 16 + row;
#pragma unroll
        for (int nt = 0; nt < 4; nt++) {
            int cb = nh * 32 + nt * 8 + col2;
            *(float2*)&Xs[r][cb]     = make_float2(c[ms][nt][0], c[ms][nt][1]);
            *(float2*)&Xs[r + 8][cb] = make_float2(c[ms][nt][2], c[ms][nt][3]);
        }
    }
    __syncthreads();

    // Epilogue: 8 lanes per edge, coalesced float4 gathers; b1/W2 from smem.
    {
        int s = lane & 7;
        int g = lane >> 3;
#pragma unroll
        for (int r = 0; r < 4; r++) {
            int e = wid * 16 + r * 4 + g;
            long long sidx = srcs[e], tidx = tgts[e];
            float4 pa0 = *(const float4*)&g_pa[sidx * 64 + s * 4];
            float4 pa1 = *(const float4*)&g_pa[sidx * 64 + 32 + s * 4];
            float4 pb0 = *(const float4*)&g_pb[tidx * 64 + s * 4];
            float4 pb1 = *(const float4*)&g_pb[tidx * 64 + 32 + s * 4];
            float4 x0 = *(const float4*)&Xs[e][s * 4];
            float4 x1 = *(const float4*)&Xs[e][32 + s * 4];
            int dlo = s * 4, dhi = 32 + s * 4;
            float gl[4], gh[4];
            gl[0] = gelu_exact(x0.x + pa0.x + pb0.x + b1s[dlo]);
            gl[1] = gelu_exact(x0.y + pa0.y + pb0.y + b1s[dlo + 1]);
            gl[2] = gelu_exact(x0.z + pa0.z + pb0.z + b1s[dlo + 2]);
            gl[3] = gelu_exact(x0.w + pa0.w + pb0.w + b1s[dlo + 3]);
            gh[0] = gelu_exact(x1.x + pa1.x + pb1.x + b1s[dhi]);
            gh[1] = gelu_exact(x1.y + pa1.y + pb1.y + b1s[dhi + 1]);
            gh[2] = gelu_exact(x1.z + pa1.z + pb1.z + b1s[dhi + 2]);
            gh[3] = gelu_exact(x1.w + pa1.w + pb1.w + b1s[dhi + 3]);
            float s0 = 0.0f, s1 = 0.0f;
#pragma unroll
            for (int q = 0; q < 4; q++) {
                s0 += gl[q] * W2s[(dlo + q) * 2]     + gh[q] * W2s[(dhi + q) * 2];
                s1 += gl[q] * W2s[(dlo + q) * 2 + 1] + gh[q] * W2s[(dhi + q) * 2 + 1];
            }
            s0 += __shfl_xor_sync(0xffffffffu, s0, 1);
            s1 += __shfl_xor_sync(0xffffffffu, s1, 1);
            s0 += __shfl_xor_sync(0xffffffffu, s0, 2);
            s1 += __shfl_xor_sync(0xffffffffu, s1, 2);
            s0 += __shfl_xor_sync(0xffffffffu, s0, 4);
            s1 += __shfl_xor_sync(0xffffffffu, s1, 4);
            long long eg = e0 + e;
            if (s == 0 && eg < E)
                *(float2*)&out[eg * 2] = make_float2(s0 + b2s[0], s1 + b2s[1]);
        }
    }
}

// ---------------- launcher ---------------------------------------------------
extern "C" void kernel_launch(void* const* d_in, const int* in_sizes, int n_in,
                              void* d_out, int out_size) {
    const float* nf  = (const float*)d_in[0];
    const float* ef  = (const float*)d_in[1];
    const void*  eix = d_in[2];
    const float* Wq  = (const float*)d_in[3];
    const float* Wk  = (const float*)d_in[4];
    const float* Wv  = (const float*)d_in[5];
    const float* We  = (const float*)d_in[6];
    const float* Wo  = (const float*)d_in[7];
    const float* W1  = (const float*)d_in[8];
    const float* b1  = (const float*)d_in[9];
    const float* W2  = (const float*)d_in[10];
    const float* b2  = (const float*)d_in[11];

    int Nn = in_sizes[0] / 64;
    long long E = in_sizes[1] / 64;
    float* out = (float*)d_out;

    int ntiles = (Nn + 63) / 64;
    int eblocks = (int)((E + 63) / 64);

    qkv_kernel<<<ntiles * 3, 256>>>(nf, Wq, Wk, Wv, W1, We, eix, Nn, E);  // 1
    edge_fused_kernel<<<eblocks, 128>>>(ef, eix, E);                      // 2
    projo_kernel<<<ntiles * 2, 256>>>(nf, Wo, Nn);                        // 3
    edge_mlp_kernel<<<eblocks, 128>>>(ef, b1, W2, b2, eix, out, E);       // 4
}